// round 2
// baseline (speedup 1.0000x reference)
#include <cuda_runtime.h>
#include <math.h>

// Problem dims (fixed by the dataset)
#define BQ 4
#define LQ 4096
#define DQ 1024
#define HQ 2048
#define BLQ (BQ * LQ)   // 16384 rows

// ---------------------------------------------------------------------------
// Scratch (allocation-free rule: __device__ globals). Reused across phases:
//   g_xn : xn  -> xn2
//   g_b1 : flin -> forget -> u(fc)
//   g_b2 : ilin -> z      -> v(fc_act)
//   g_h  : h   -> ff
//   g_x1 : x1
// ---------------------------------------------------------------------------
__device__ float g_xn[(size_t)BLQ * DQ];
__device__ float g_b1[(size_t)BLQ * HQ];
__device__ float g_b2[(size_t)BLQ * HQ];
__device__ float g_h [(size_t)BLQ * HQ];
__device__ float g_x1[(size_t)BLQ * DQ];

// ---------------------------------------------------------------------------
// RMSNorm: one block per row, D=1024, 256 threads * float4
// ---------------------------------------------------------------------------
__global__ void rmsnorm_kernel(const float* __restrict__ x,
                               const float* __restrict__ g,
                               float* __restrict__ out)
{
    int row = blockIdx.x;
    int tid = threadIdx.x;
    const float4* xr = reinterpret_cast<const float4*>(x + (size_t)row * DQ);
    float4 v = xr[tid];
    float s = v.x * v.x + v.y * v.y + v.z * v.z + v.w * v.w;

    #pragma unroll
    for (int o = 16; o > 0; o >>= 1)
        s += __shfl_xor_sync(0xFFFFFFFFu, s, o);

    __shared__ float red[8];
    __shared__ float scale_s;
    int lane = tid & 31, wid = tid >> 5;
    if (lane == 0) red[wid] = s;
    __syncthreads();
    if (tid == 0) {
        float t = 0.f;
        #pragma unroll
        for (int i = 0; i < 8; i++) t += red[i];
        scale_s = rsqrtf(t * (1.0f / DQ) + 1e-6f);
    }
    __syncthreads();
    float sc = scale_s;
    float4 gg = reinterpret_cast<const float4*>(g)[tid];
    float4 o4;
    o4.x = v.x * sc * gg.x;
    o4.y = v.y * sc * gg.y;
    o4.z = v.z * sc * gg.z;
    o4.w = v.w * sc * gg.w;
    reinterpret_cast<float4*>(out + (size_t)row * DQ)[tid] = o4;
}

// ---------------------------------------------------------------------------
// GEMM: C[M,N] = A[M,K] @ W[N,K]^T + bias[N] (+ resid[M,N] if non-null)
// Tile 128x128, BK=16, 256 threads, 8x8 per-thread microtile. M,N%128==0, K%16==0.
// ---------------------------------------------------------------------------
__global__ __launch_bounds__(256, 2)
void gemm_bias_res(const float* __restrict__ A, const float* __restrict__ W,
                   const float* __restrict__ bias, const float* __restrict__ resid,
                   float* __restrict__ C, int M, int N, int K)
{
    __shared__ float As[16][128];
    __shared__ float Bs[16][128];

    int tid = threadIdx.x;
    int tx = tid & 15;        // 0..15 -> N dir (8 cols each)
    int ty = tid >> 4;        // 0..15 -> M dir (8 rows each)
    int m0 = blockIdx.y * 128;
    int n0 = blockIdx.x * 128;

    float acc[8][8];
    #pragma unroll
    for (int i = 0; i < 8; i++)
        #pragma unroll
        for (int j = 0; j < 8; j++) acc[i][j] = 0.f;

    for (int k0 = 0; k0 < K; k0 += 16) {
        // Load 128x16 tiles of A and W (512 float4 each; 2 per thread)
        #pragma unroll
        for (int it = 0; it < 2; it++) {
            int idx = tid * 2 + it;     // 0..511
            int row = idx >> 2;         // 0..127
            int q   = idx & 3;          // float4 within the 16-wide k-slab
            float4 va = *reinterpret_cast<const float4*>(
                &A[(size_t)(m0 + row) * K + k0 + q * 4]);
            As[q * 4 + 0][row] = va.x;
            As[q * 4 + 1][row] = va.y;
            As[q * 4 + 2][row] = va.z;
            As[q * 4 + 3][row] = va.w;
            float4 vw = *reinterpret_cast<const float4*>(
                &W[(size_t)(n0 + row) * K + k0 + q * 4]);
            Bs[q * 4 + 0][row] = vw.x;
            Bs[q * 4 + 1][row] = vw.y;
            Bs[q * 4 + 2][row] = vw.z;
            Bs[q * 4 + 3][row] = vw.w;
        }
        __syncthreads();

        #pragma unroll
        for (int kk = 0; kk < 16; kk++) {
            float a[8], b[8];
            *reinterpret_cast<float4*>(&a[0]) = *reinterpret_cast<float4*>(&As[kk][ty * 8]);
            *reinterpret_cast<float4*>(&a[4]) = *reinterpret_cast<float4*>(&As[kk][ty * 8 + 4]);
            *reinterpret_cast<float4*>(&b[0]) = *reinterpret_cast<float4*>(&Bs[kk][tx * 8]);
            *reinterpret_cast<float4*>(&b[4]) = *reinterpret_cast<float4*>(&Bs[kk][tx * 8 + 4]);
            #pragma unroll
            for (int i = 0; i < 8; i++)
                #pragma unroll
                for (int j = 0; j < 8; j++)
                    acc[i][j] = fmaf(a[i], b[j], acc[i][j]);
        }
        __syncthreads();
    }

    // Epilogue
    float4 bb0 = *reinterpret_cast<const float4*>(&bias[n0 + tx * 8]);
    float4 bb1 = *reinterpret_cast<const float4*>(&bias[n0 + tx * 8 + 4]);
    #pragma unroll
    for (int i = 0; i < 8; i++) {
        int m = m0 + ty * 8 + i;
        size_t off = (size_t)m * N + n0 + tx * 8;
        float4 r0, r1;
        r0.x = acc[i][0] + bb0.x; r0.y = acc[i][1] + bb0.y;
        r0.z = acc[i][2] + bb0.z; r0.w = acc[i][3] + bb0.w;
        r1.x = acc[i][4] + bb1.x; r1.y = acc[i][5] + bb1.y;
        r1.z = acc[i][6] + bb1.z; r1.w = acc[i][7] + bb1.w;
        if (resid) {
            float4 q0 = *reinterpret_cast<const float4*>(&resid[off]);
            float4 q1 = *reinterpret_cast<const float4*>(&resid[off + 4]);
            r0.x += q0.x; r0.y += q0.y; r0.z += q0.z; r0.w += q0.w;
            r1.x += q1.x; r1.y += q1.y; r1.z += q1.z; r1.w += q1.w;
        }
        *reinterpret_cast<float4*>(&C[off])     = r0;
        *reinterpret_cast<float4*>(&C[off + 4]) = r1;
    }
}

// ---------------------------------------------------------------------------
// Gate elementwise: b1 := forget = 1 - sigmoid(flin)*decay[h]
//                   b2 := z      = tanh(ilin) * sigmoid(flin)*decay[h]
// ---------------------------------------------------------------------------
__global__ void gate_kernel(float* __restrict__ b1, float* __restrict__ b2)
{
    size_t idx = (size_t)blockIdx.x * blockDim.x + threadIdx.x;
    int hh = (int)(idx & (HQ - 1));
    float fl = b1[idx];
    float il = b2[idx];
    float decay = (float)hh * (1.0f / (float)(HQ - 1));
    float rem = (1.0f / (1.0f + expf(-fl))) * decay;
    b1[idx] = 1.0f - rem;
    b2[idx] = tanhf(il) * rem;
}

// ---------------------------------------------------------------------------
// Scan: one thread per (b,h) channel, serial over L. [B,L,H] layout ->
// coalesced loads across the warp at every timestep.
// ---------------------------------------------------------------------------
__global__ void scan_kernel(const float* __restrict__ f, const float* __restrict__ z,
                            const float* __restrict__ h0, float* __restrict__ h,
                            float* __restrict__ hlast)
{
    int c = blockIdx.x * blockDim.x + threadIdx.x;   // 0 .. B*H-1
    int b = c >> 11;                                  // / HQ
    int hh = c & (HQ - 1);
    float hc = h0[c];
    size_t base = (size_t)b * LQ * HQ + hh;
    #pragma unroll 4
    for (int t = 0; t < LQ; t++) {
        size_t idx = base + (size_t)t * HQ;
        hc = fmaf(f[idx], hc, z[idx]);
        h[idx] = hc;
    }
    hlast[c] = hc;
}

// ---------------------------------------------------------------------------
// SwiGLU elementwise: ff = u * silu(v)
// ---------------------------------------------------------------------------
__global__ void swiglu_kernel(const float* __restrict__ u, const float* __restrict__ v,
                              float* __restrict__ ff)
{
    size_t idx = (size_t)blockIdx.x * blockDim.x + threadIdx.x;
    float uu = u[idx];
    float vv = v[idx];
    float sig = 1.0f / (1.0f + expf(-vv));
    ff[idx] = uu * vv * sig;
}

// ---------------------------------------------------------------------------
// Launch
// ---------------------------------------------------------------------------
extern "C" void kernel_launch(void* const* d_in, const int* in_sizes, int n_in,
                              void* d_out, int out_size)
{
    const float* x      = (const float*)d_in[0];
    const float* hidden = (const float*)d_in[1];
    const float* w_f    = (const float*)d_in[2];
    const float* b_f    = (const float*)d_in[3];
    const float* w_i    = (const float*)d_in[4];
    const float* b_i    = (const float*)d_in[5];
    const float* w_ho   = (const float*)d_in[6];
    const float* b_ho   = (const float*)d_in[7];
    const float* w_fc   = (const float*)d_in[8];
    const float* b_fc   = (const float*)d_in[9];
    const float* w_fa   = (const float*)d_in[10];
    const float* b_fa   = (const float*)d_in[11];
    const float* w_fo   = (const float*)d_in[12];
    const float* b_fo   = (const float*)d_in[13];
    const float* g1     = (const float*)d_in[14];
    const float* g2     = (const float*)d_in[15];

    float* out_main  = (float*)d_out;                         // [B,L,D]
    float* out_hlast = out_main + (size_t)BLQ * DQ;           // [B,H]

    float *p_xn, *p_b1, *p_b2, *p_h, *p_x1;
    cudaGetSymbolAddress((void**)&p_xn, g_xn);
    cudaGetSymbolAddress((void**)&p_b1, g_b1);
    cudaGetSymbolAddress((void**)&p_b2, g_b2);
    cudaGetSymbolAddress((void**)&p_h,  g_h);
    cudaGetSymbolAddress((void**)&p_x1, g_x1);

    dim3 blk(256);
    dim3 gemmDH(HQ / 128, BLQ / 128);   // N=2048 outputs
    dim3 gemmHD(DQ / 128, BLQ / 128);   // N=1024 outputs
    size_t nBH = (size_t)BLQ * HQ;

    // 1) xn = rmsnorm(x, g1)
    rmsnorm_kernel<<<BLQ, 256>>>(x, g1, p_xn);
    // 2,3) flin / ilin
    gemm_bias_res<<<gemmDH, blk>>>(p_xn, w_f, b_f, nullptr, p_b1, BLQ, HQ, DQ);
    gemm_bias_res<<<gemmDH, blk>>>(p_xn, w_i, b_i, nullptr, p_b2, BLQ, HQ, DQ);
    // 4) gates
    gate_kernel<<<(unsigned)(nBH / 256), blk>>>(p_b1, p_b2);
    // 5) recurrence -> h, h_last
    scan_kernel<<<(BQ * HQ) / 256, blk>>>(p_b1, p_b2, hidden, p_h, out_hlast);
    // 6) x1 = h @ w_hout^T + b_hout + x
    gemm_bias_res<<<gemmHD, blk>>>(p_h, w_ho, b_ho, x, p_x1, BLQ, DQ, HQ);
    // 7) xn2 = rmsnorm(x1, g2)
    rmsnorm_kernel<<<BLQ, 256>>>(p_x1, g2, p_xn);
    // 8,9) u / v
    gemm_bias_res<<<gemmDH, blk>>>(p_xn, w_fc, b_fc, nullptr, p_b1, BLQ, HQ, DQ);
    gemm_bias_res<<<gemmDH, blk>>>(p_xn, w_fa, b_fa, nullptr, p_b2, BLQ, HQ, DQ);
    // 10) ff = u * silu(v)  (into g_h, h no longer needed)
    swiglu_kernel<<<(unsigned)(nBH / 256), blk>>>(p_b1, p_b2, p_h);
    // 11) out = ff @ w_fout^T + b_fout + x1
    gemm_bias_res<<<gemmHD, blk>>>(p_h, w_fo, b_fo, p_x1, out_main, BLQ, DQ, HQ);
}